// round 1
// baseline (speedup 1.0000x reference)
#include <cuda_runtime.h>
#include <math.h>

// ---------------------------------------------------------------------------
// Problem constants
// ---------------------------------------------------------------------------
#define BATCH 2
#define SEQ   2048
#define CH    768
#define HEADS 24
#define HD    32
#define L_PER_B (SEQ * CH)            // 1,572,864 floats per batch
#define TOT (BATCH * SEQ * CH)        // 3,145,728 floats

// Scratch buffers (allocation-free rule: __device__ globals)
__device__ float g_xn[TOT];   // rmsnorm1(x)
__device__ float g_q[TOT];    // q projection
__device__ float g_vp[TOT];   // gathered V' (n, h*32+d)
__device__ float g_vr[TOT];   // premixed V = WA @ V'
__device__ float g_res[TOT];  // attn + x (residual)
__device__ float g_h[TOT];    // rmsnorm2(res)
__device__ float g_h1[TOT];   // gelu(h @ W1^T)

// ---------------------------------------------------------------------------
// RMSNorm: one block per row of 768
// ---------------------------------------------------------------------------
__global__ __launch_bounds__(256)
void rmsnorm_kernel(const float* __restrict__ x, const float* __restrict__ g,
                    float* __restrict__ y)
{
    const int row = blockIdx.x;
    const int t = threadIdx.x;
    const float* xr = x + (long)row * CH;
    float v0 = xr[t], v1 = xr[t + 256], v2 = xr[t + 512];
    float ss = v0 * v0 + v1 * v1 + v2 * v2;

    __shared__ float red[8];
    #pragma unroll
    for (int o = 16; o > 0; o >>= 1) ss += __shfl_xor_sync(0xffffffffu, ss, o);
    if ((t & 31) == 0) red[t >> 5] = ss;
    __syncthreads();
    if (t < 8) {
        float s = red[t];
        #pragma unroll
        for (int o = 4; o > 0; o >>= 1) s += __shfl_xor_sync(0xffu, s, o);
        if (t == 0) red[0] = s;
    }
    __syncthreads();
    const float inv = rsqrtf(red[0] * (1.0f / 768.0f) + 1.1920928955078125e-07f);
    float* yr = y + (long)row * CH;
    yr[t]       = v0 * inv * g[t];
    yr[t + 256] = v1 * inv * g[t + 256];
    yr[t + 512] = v2 * inv * g[t + 512];
}

// ---------------------------------------------------------------------------
// Gather the (H, N, HD) flat view into VP[n][h*32+d]  (per batch (N x C))
// ---------------------------------------------------------------------------
__global__ void gather_v_kernel(const float* __restrict__ xn, float* __restrict__ vp)
{
    long i = (long)blockIdx.x * blockDim.x + threadIdx.x;
    if (i >= (long)TOT) return;
    int b = (int)(i / L_PER_B);
    int rem = (int)(i - (long)b * L_PER_B);
    int m = rem / CH;
    int col = rem - m * CH;
    int h = col >> 5;
    int d = col & 31;
    vp[i] = xn[(long)b * L_PER_B + (long)h * (SEQ * HD) + m * HD + d];
}

// ---------------------------------------------------------------------------
// SGEMM: C = A(MxK) @ op(B) (+ epilogue)
//   BT=true : B is (N x K) row-major, C[m,n] = sum_k A[m,k]*B[n,k]
//   BT=false: B is (K x N) row-major, C[m,n] = sum_k A[m,k]*B[k,n]
// EPI: 0 = none, 1 = exact GELU, 2 = add residual R
// 128x128x16 tile, 256 threads, 8x8 per thread. M%128==0, N%128==0, K%16==0.
// ---------------------------------------------------------------------------
__device__ __forceinline__ float gelu_exact(float v)
{
    return 0.5f * v * (1.0f + erff(v * 0.7071067811865476f));
}

template<bool BT, int EPI>
__global__ __launch_bounds__(256)
void gemm128(const float* __restrict__ A, const float* __restrict__ B,
             float* __restrict__ C, const float* __restrict__ R,
             int M, int N, int K,
             long strideA, long strideB, long strideC)
{
    constexpr int BM = 128, BN = 128, BK = 16;
    __shared__ __align__(16) float As[BK][BM];
    __shared__ __align__(16) float Bs[BK][BN];

    A += (long)blockIdx.z * strideA;
    B += (long)blockIdx.z * strideB;
    C += (long)blockIdx.z * strideC;
    if (EPI == 2) R += (long)blockIdx.z * strideC;

    const int tid = threadIdx.x;
    const int m0 = blockIdx.y * BM;
    const int n0 = blockIdx.x * BN;

    // A/B-transposed load indexing
    const int aRow = tid >> 2;          // 0..63
    const int aCol = (tid & 3) * 4;     // 0,4,8,12
    // B non-transposed load indexing
    const int kRow = tid >> 5;          // 0..7
    const int nCol = (tid & 31) * 4;    // 0..124

    const int tx = tid & 15, ty = tid >> 4;

    float acc[8][8] = {};

    for (int k0 = 0; k0 < K; k0 += BK) {
        #pragma unroll
        for (int r = 0; r < 2; r++) {
            int row = aRow + r * 64;
            float4 v = *(const float4*)(A + (long)(m0 + row) * K + k0 + aCol);
            As[aCol + 0][row] = v.x; As[aCol + 1][row] = v.y;
            As[aCol + 2][row] = v.z; As[aCol + 3][row] = v.w;
        }
        if (BT) {
            #pragma unroll
            for (int r = 0; r < 2; r++) {
                int row = aRow + r * 64;
                float4 v = *(const float4*)(B + (long)(n0 + row) * K + k0 + aCol);
                Bs[aCol + 0][row] = v.x; Bs[aCol + 1][row] = v.y;
                Bs[aCol + 2][row] = v.z; Bs[aCol + 3][row] = v.w;
            }
        } else {
            #pragma unroll
            for (int r = 0; r < 2; r++) {
                int kk = kRow + r * 8;
                float4 v = *(const float4*)(B + (long)(k0 + kk) * N + n0 + nCol);
                *(float4*)&Bs[kk][nCol] = v;
            }
        }
        __syncthreads();

        #pragma unroll
        for (int k = 0; k < BK; k++) {
            float4 a0 = *(const float4*)&As[k][ty * 8];
            float4 a1 = *(const float4*)&As[k][ty * 8 + 4];
            float4 b0 = *(const float4*)&Bs[k][tx * 8];
            float4 b1 = *(const float4*)&Bs[k][tx * 8 + 4];
            float a[8] = {a0.x, a0.y, a0.z, a0.w, a1.x, a1.y, a1.z, a1.w};
            float bb[8] = {b0.x, b0.y, b0.z, b0.w, b1.x, b1.y, b1.z, b1.w};
            #pragma unroll
            for (int i = 0; i < 8; i++)
                #pragma unroll
                for (int j = 0; j < 8; j++)
                    acc[i][j] = fmaf(a[i], bb[j], acc[i][j]);
        }
        __syncthreads();
    }

    #pragma unroll
    for (int i = 0; i < 8; i++) {
        const int row = m0 + ty * 8 + i;
        #pragma unroll
        for (int j = 0; j < 8; j += 4) {
            const int col = n0 + tx * 8 + j;
            float4 v;
            float* pv = &v.x;
            #pragma unroll
            for (int qq = 0; qq < 4; qq++) {
                float val = acc[i][j + qq];
                if (EPI == 1)      val = gelu_exact(val);
                else if (EPI == 2) val += R[(long)row * N + col + qq];
                pv[qq] = val;
            }
            *(float4*)(C + (long)row * N + col) = v;
        }
    }
}

// ---------------------------------------------------------------------------
// Flash attention over the "super" head view.
// Q/K flat per (b,h): base = b*L + h*SEQ*HD, row-major (SEQ, HD).
// V: VR, v[h][m][d] = VR[b*L + m*CH + h*32 + d].
// Output: attn + x at the same flat layout (== (B,N,C) row-major).
// Block: 128 threads = 128 query rows; key tiles of 64.
// ---------------------------------------------------------------------------
__global__ __launch_bounds__(128)
void flash_kernel(const float* __restrict__ Q, const float* __restrict__ Km,
                  const float* __restrict__ Vm, const float* __restrict__ X,
                  const float* __restrict__ scale_param, float* __restrict__ O)
{
    const int b = blockIdx.z, h = blockIdx.y;
    const int t = threadIdx.x;
    const int qrow = blockIdx.x * 128 + t;

    __shared__ __align__(16) float ksh[64][32];
    __shared__ __align__(16) float vsh[64][32];

    const long baseqk = (long)b * L_PER_B + (long)h * (SEQ * HD);
    const float coef = logf(768.0f) * scale_param[h] * 5.656854249492381f;

    float q[32];
    {
        const float4* qp = (const float4*)(Q + baseqk + (long)qrow * HD);
        #pragma unroll
        for (int i = 0; i < 8; i++) {
            float4 v = qp[i];
            q[4 * i]     = v.x * coef;
            q[4 * i + 1] = v.y * coef;
            q[4 * i + 2] = v.z * coef;
            q[4 * i + 3] = v.w * coef;
        }
    }

    float acc[32];
    #pragma unroll
    for (int d = 0; d < 32; d++) acc[d] = 0.0f;
    float Mx = -1e30f, S = 0.0f;

    const int jrow = t >> 1, part = t & 1;

    for (int kt = 0; kt < SEQ / 64; kt++) {
        __syncthreads();
        // K tile: 64 keys x 32 dims, fully contiguous in the flat view
        {
            const float4* src = (const float4*)(Km + baseqk + (long)kt * 64 * HD);
            float4* dst = (float4*)&ksh[0][0];
            #pragma unroll
            for (int i = 0; i < 4; i++) dst[t + i * 128] = src[t + i * 128];
        }
        // V tile: row m = kt*64 + j, cols h*32..h*32+31 of VR
        {
            const float4* vsrc = (const float4*)(Vm + (long)b * L_PER_B +
                                                 (long)(kt * 64 + jrow) * CH + h * HD) + part * 4;
            float4* vdst = (float4*)&vsh[jrow][0] + part * 4;
            #pragma unroll
            for (int i = 0; i < 4; i++) vdst[i] = vsrc[i];
        }
        __syncthreads();

        #pragma unroll
        for (int ch = 0; ch < 2; ch++) {
            float s[32];
            #pragma unroll
            for (int j = 0; j < 32; j++) {
                const float4* kp = (const float4*)&ksh[ch * 32 + j][0];
                float d0 = 0.f, d1 = 0.f, d2 = 0.f, d3 = 0.f;
                #pragma unroll
                for (int i = 0; i < 8; i++) {
                    float4 kv = kp[i];
                    d0 = fmaf(q[4 * i],     kv.x, d0);
                    d1 = fmaf(q[4 * i + 1], kv.y, d1);
                    d2 = fmaf(q[4 * i + 2], kv.z, d2);
                    d3 = fmaf(q[4 * i + 3], kv.w, d3);
                }
                s[j] = (d0 + d1) + (d2 + d3);
            }
            float cm = s[0];
            #pragma unroll
            for (int j = 1; j < 32; j++) cm = fmaxf(cm, s[j]);
            const float Mn = fmaxf(Mx, cm);
            const float corr = __expf(Mx - Mn);
            S *= corr;
            #pragma unroll
            for (int d = 0; d < 32; d++) acc[d] *= corr;
            Mx = Mn;
            #pragma unroll
            for (int j = 0; j < 32; j++) {
                const float p = __expf(s[j] - Mx);
                S += p;
                const float4* vp = (const float4*)&vsh[ch * 32 + j][0];
                #pragma unroll
                for (int i = 0; i < 8; i++) {
                    float4 vv = vp[i];
                    acc[4 * i]     = fmaf(p, vv.x, acc[4 * i]);
                    acc[4 * i + 1] = fmaf(p, vv.y, acc[4 * i + 1]);
                    acc[4 * i + 2] = fmaf(p, vv.z, acc[4 * i + 2]);
                    acc[4 * i + 3] = fmaf(p, vv.w, acc[4 * i + 3]);
                }
            }
        }
    }

    const float inv = 1.0f / S;
    const float4* xp = (const float4*)(X + baseqk + (long)qrow * HD);
    float4* op = (float4*)(O + baseqk + (long)qrow * HD);
    #pragma unroll
    for (int i = 0; i < 8; i++) {
        float4 xv = xp[i];
        float4 ov;
        ov.x = acc[4 * i]     * inv + xv.x;
        ov.y = acc[4 * i + 1] * inv + xv.y;
        ov.z = acc[4 * i + 2] * inv + xv.z;
        ov.w = acc[4 * i + 3] * inv + xv.w;
        op[i] = ov;
    }
}

// ---------------------------------------------------------------------------
// Launch
// ---------------------------------------------------------------------------
extern "C" void kernel_launch(void* const* d_in, const int* in_sizes, int n_in,
                              void* d_out, int out_size)
{
    const float* x     = (const float*)d_in[0];  // (B,N,C)
    const float* scale = (const float*)d_in[1];  // (H)
    const float* Wq    = (const float*)d_in[2];  // (C,C)
    const float* WA    = (const float*)d_in[3];  // (N,N)
    const float* W1    = (const float*)d_in[4];  // (C,C)
    const float* W2    = (const float*)d_in[5];  // (C,C)
    const float* g1    = (const float*)d_in[6];  // (C)
    const float* g2    = (const float*)d_in[7];  // (C)
    float* out = (float*)d_out;

    float *xn, *q, *vp, *vr, *res, *hh, *h1;
    cudaGetSymbolAddress((void**)&xn,  g_xn);
    cudaGetSymbolAddress((void**)&q,   g_q);
    cudaGetSymbolAddress((void**)&vp,  g_vp);
    cudaGetSymbolAddress((void**)&vr,  g_vr);
    cudaGetSymbolAddress((void**)&res, g_res);
    cudaGetSymbolAddress((void**)&hh,  g_h);
    cudaGetSymbolAddress((void**)&h1,  g_h1);

    const int ROWS = BATCH * SEQ;  // 4096

    // 1. xn = rmsnorm(x, g1)
    rmsnorm_kernel<<<ROWS, 256>>>(x, g1, xn);

    // 2. q = xn @ Wq^T   (4096x768 @ 768x768^T)
    gemm128<true, 0><<<dim3(CH / 128, ROWS / 128, 1), 256>>>(
        xn, Wq, q, nullptr, ROWS, CH, CH, 0, 0, 0);

    // 3. gather V' from the (H,N,HD) view
    gather_v_kernel<<<(TOT + 255) / 256, 256>>>(xn, vp);

    // 4. vr[b] = WA @ vp[b]   (2048x2048 @ 2048x768), batched over b
    gemm128<false, 0><<<dim3(CH / 128, SEQ / 128, BATCH), 256>>>(
        WA, vp, vr, nullptr, SEQ, CH, SEQ, 0, (long)SEQ * CH, (long)SEQ * CH);

    // 5. attention (+x residual)
    flash_kernel<<<dim3(SEQ / 128, HEADS, BATCH), 128>>>(q, xn, vr, x, scale, res);

    // 6. hh = rmsnorm(res, g2)
    rmsnorm_kernel<<<ROWS, 256>>>(res, g2, hh);

    // 7. h1 = gelu(hh @ W1^T)
    gemm128<true, 1><<<dim3(CH / 128, ROWS / 128, 1), 256>>>(
        hh, W1, h1, nullptr, ROWS, CH, CH, 0, 0, 0);

    // 8. out = h1 @ W2^T + res
    gemm128<true, 2><<<dim3(CH / 128, ROWS / 128, 1), 256>>>(
        h1, W2, out, res, ROWS, CH, CH, 0, 0, 0);
}

// round 2
// speedup vs baseline: 1.3892x; 1.3892x over previous
#include <cuda_runtime.h>
#include <math.h>

// ---------------------------------------------------------------------------
// Problem constants
// ---------------------------------------------------------------------------
#define BATCH 2
#define SEQ   2048
#define CH    768
#define HEADS 24
#define HD    32
#define L_PER_B (SEQ * CH)            // 1,572,864 floats per batch
#define TOT (BATCH * SEQ * CH)        // 3,145,728 floats

// Scratch buffers (allocation-free rule: __device__ globals)
__device__ float g_xn[TOT];   // rmsnorm1(x)
__device__ float g_q[TOT];    // q projection
__device__ float g_vp[TOT];   // gathered V' (n, h*32+d)
__device__ float g_vr[TOT];   // premixed V = WA @ V'
__device__ float g_res[TOT];  // attn + x (residual)
__device__ float g_h[TOT];    // rmsnorm2(res)
__device__ float g_h1[TOT];   // gelu(h @ W1^T)

// ---------------------------------------------------------------------------
// RMSNorm: one block per row of 768
// ---------------------------------------------------------------------------
__global__ __launch_bounds__(256)
void rmsnorm_kernel(const float* __restrict__ x, const float* __restrict__ g,
                    float* __restrict__ y)
{
    const int row = blockIdx.x;
    const int t = threadIdx.x;
    const float* xr = x + (long)row * CH;
    float v0 = xr[t], v1 = xr[t + 256], v2 = xr[t + 512];
    float ss = v0 * v0 + v1 * v1 + v2 * v2;

    __shared__ float red[8];
    #pragma unroll
    for (int o = 16; o > 0; o >>= 1) ss += __shfl_xor_sync(0xffffffffu, ss, o);
    if ((t & 31) == 0) red[t >> 5] = ss;
    __syncthreads();
    if (t < 8) {
        float s = red[t];
        #pragma unroll
        for (int o = 4; o > 0; o >>= 1) s += __shfl_xor_sync(0xffu, s, o);
        if (t == 0) red[0] = s;
    }
    __syncthreads();
    const float inv = rsqrtf(red[0] * (1.0f / 768.0f) + 1.1920928955078125e-07f);
    float* yr = y + (long)row * CH;
    yr[t]       = v0 * inv * g[t];
    yr[t + 256] = v1 * inv * g[t + 256];
    yr[t + 512] = v2 * inv * g[t + 512];
}

// ---------------------------------------------------------------------------
// Gather the (H, N, HD) flat view into VP[n][h*32+d]  (per batch (N x C))
// ---------------------------------------------------------------------------
__global__ void gather_v_kernel(const float* __restrict__ xn, float* __restrict__ vp)
{
    long i = (long)blockIdx.x * blockDim.x + threadIdx.x;
    if (i >= (long)TOT) return;
    int b = (int)(i / L_PER_B);
    int rem = (int)(i - (long)b * L_PER_B);
    int m = rem / CH;
    int col = rem - m * CH;
    int h = col >> 5;
    int d = col & 31;
    vp[i] = xn[(long)b * L_PER_B + (long)h * (SEQ * HD) + m * HD + d];
}

// ---------------------------------------------------------------------------
// helpers
// ---------------------------------------------------------------------------
__device__ __forceinline__ float gelu_exact(float v)
{
    return 0.5f * v * (1.0f + erff(v * 0.7071067811865476f));
}

__device__ __forceinline__ unsigned cvt_tf32(float x)
{
    unsigned r;
    asm("cvt.rna.tf32.f32 %0, %1;" : "=r"(r) : "f"(x));
    return r;
}

__device__ __forceinline__ float4 cvt4_tf32(float4 v)
{
    float4 s;
    s.x = __uint_as_float(cvt_tf32(v.x));
    s.y = __uint_as_float(cvt_tf32(v.y));
    s.z = __uint_as_float(cvt_tf32(v.z));
    s.w = __uint_as_float(cvt_tf32(v.w));
    return s;
}

// ---------------------------------------------------------------------------
// TF32 tensor-core GEMM, 128x128x32 tile, 256 threads (8 warps, 2x4),
// warp tile 64x32, mma.sync.m16n8k8 tf32 fragments.
//   NNMODE=true : C = A(MxK) @ B(KxN)        (both row-major)
//   NNMODE=false: C = A(MxK) @ B(NxK)^T      (NT)
// EPI: 0 none, 1 exact GELU, 2 add residual R
// Requires M%128==0, N%128==0, K%32==0.
// Conversion fp32->tf32 happens once at the smem-staging step.
// ---------------------------------------------------------------------------
template<bool NNMODE, int EPI>
__global__ __launch_bounds__(256)
void gemm_tf32(const float* __restrict__ A, const float* __restrict__ B,
               float* __restrict__ C, const float* __restrict__ R,
               int M, int N, int K,
               long sA, long sB, long sC)
{
    __shared__ __align__(16) float As[128 * 36];   // [m][k] pad 4
    __shared__ __align__(16) float Bs[4608];       // NT: [n][k] pad4 ; NN: [k][n] pad8

    A += (long)blockIdx.z * sA;
    B += (long)blockIdx.z * sB;
    C += (long)blockIdx.z * sC;
    if (EPI == 2) R += (long)blockIdx.z * sC;

    const int t = threadIdx.x;
    const int w = t >> 5, lane = t & 31;
    const int g = lane >> 2, tg = lane & 3;
    const int wm = w >> 2, wn = w & 3;       // 2 x 4 warp grid
    const int m0 = blockIdx.y * 128, n0 = blockIdx.x * 128;

    float acc[4][4][4] = {};

    for (int k0 = 0; k0 < K; k0 += 32) {
        // ---- stage A tile (128 x 32), coalesced, cvt to tf32 ----
        #pragma unroll
        for (int i = 0; i < 4; i++) {
            const int row = (t >> 3) + i * 32;
            const int c4 = t & 7;
            float4 v = *(const float4*)(A + (long)(m0 + row) * K + k0 + c4 * 4);
            *(float4*)&As[row * 36 + c4 * 4] = cvt4_tf32(v);
        }
        // ---- stage B tile ----
        if (NNMODE) {
            #pragma unroll
            for (int i = 0; i < 4; i++) {
                const int kk = t >> 3;
                const int c4 = (t & 7) + i * 8;
                float4 v = *(const float4*)(B + (long)(k0 + kk) * N + n0 + c4 * 4);
                *(float4*)&Bs[kk * 136 + c4 * 4] = cvt4_tf32(v);
            }
        } else {
            #pragma unroll
            for (int i = 0; i < 4; i++) {
                const int row = (t >> 3) + i * 32;
                const int c4 = t & 7;
                float4 v = *(const float4*)(B + (long)(n0 + row) * K + k0 + c4 * 4);
                *(float4*)&Bs[row * 36 + c4 * 4] = cvt4_tf32(v);
            }
        }
        __syncthreads();

        // ---- 4 k-chunks of 8 ----
        #pragma unroll
        for (int kc = 0; kc < 4; kc++) {
            const int kb = kc * 8;
            unsigned a[4][4], b[4][2];
            #pragma unroll
            for (int mt = 0; mt < 4; mt++) {
                const int mr = wm * 64 + mt * 16 + g;
                a[mt][0] = __float_as_uint(As[mr * 36 + kb + tg]);
                a[mt][1] = __float_as_uint(As[(mr + 8) * 36 + kb + tg]);
                a[mt][2] = __float_as_uint(As[mr * 36 + kb + tg + 4]);
                a[mt][3] = __float_as_uint(As[(mr + 8) * 36 + kb + tg + 4]);
            }
            #pragma unroll
            for (int nt = 0; nt < 4; nt++) {
                const int nc = wn * 32 + nt * 8 + g;
                if (NNMODE) {
                    b[nt][0] = __float_as_uint(Bs[(kb + tg) * 136 + nc]);
                    b[nt][1] = __float_as_uint(Bs[(kb + tg + 4) * 136 + nc]);
                } else {
                    b[nt][0] = __float_as_uint(Bs[nc * 36 + kb + tg]);
                    b[nt][1] = __float_as_uint(Bs[nc * 36 + kb + tg + 4]);
                }
            }
            #pragma unroll
            for (int mt = 0; mt < 4; mt++)
                #pragma unroll
                for (int nt = 0; nt < 4; nt++)
                    asm volatile(
                        "mma.sync.aligned.m16n8k8.row.col.f32.tf32.tf32.f32 "
                        "{%0,%1,%2,%3}, {%4,%5,%6,%7}, {%8,%9}, {%0,%1,%2,%3};"
                        : "+f"(acc[mt][nt][0]), "+f"(acc[mt][nt][1]),
                          "+f"(acc[mt][nt][2]), "+f"(acc[mt][nt][3])
                        : "r"(a[mt][0]), "r"(a[mt][1]), "r"(a[mt][2]), "r"(a[mt][3]),
                          "r"(b[nt][0]), "r"(b[nt][1]));
        }
        __syncthreads();
    }

    // ---- epilogue ----
    #pragma unroll
    for (int mt = 0; mt < 4; mt++) {
        #pragma unroll
        for (int nt = 0; nt < 4; nt++) {
            const int row0 = m0 + wm * 64 + mt * 16 + g;
            const int col  = n0 + wn * 32 + nt * 8 + 2 * tg;
            float v0 = acc[mt][nt][0], v1 = acc[mt][nt][1];
            float v2 = acc[mt][nt][2], v3 = acc[mt][nt][3];
            if (EPI == 1) {
                v0 = gelu_exact(v0); v1 = gelu_exact(v1);
                v2 = gelu_exact(v2); v3 = gelu_exact(v3);
            } else if (EPI == 2) {
                float2 r0 = *(const float2*)(R + (long)row0 * N + col);
                float2 r1 = *(const float2*)(R + (long)(row0 + 8) * N + col);
                v0 += r0.x; v1 += r0.y; v2 += r1.x; v3 += r1.y;
            }
            float2 o0 = {v0, v1}, o1 = {v2, v3};
            *(float2*)(C + (long)row0 * N + col) = o0;
            *(float2*)(C + (long)(row0 + 8) * N + col) = o1;
        }
    }
}

// ---------------------------------------------------------------------------
// FP32 SGEMM (kept for the Q projection — feeds softmax logits, needs fp32)
// C = A(MxK) @ B(NxK)^T ; 128x128x16, 256 threads, 8x8 per thread.
// ---------------------------------------------------------------------------
__global__ __launch_bounds__(256)
void gemm128_nt(const float* __restrict__ A, const float* __restrict__ B,
                float* __restrict__ C, int M, int N, int K)
{
    constexpr int BM = 128, BN = 128, BK = 16;
    __shared__ __align__(16) float As[BK][BM];
    __shared__ __align__(16) float Bs[BK][BN];

    const int tid = threadIdx.x;
    const int m0 = blockIdx.y * BM;
    const int n0 = blockIdx.x * BN;

    const int aRow = tid >> 2;
    const int aCol = (tid & 3) * 4;
    const int tx = tid & 15, ty = tid >> 4;

    float acc[8][8] = {};

    for (int k0 = 0; k0 < K; k0 += BK) {
        #pragma unroll
        for (int r = 0; r < 2; r++) {
            int row = aRow + r * 64;
            float4 v = *(const float4*)(A + (long)(m0 + row) * K + k0 + aCol);
            As[aCol + 0][row] = v.x; As[aCol + 1][row] = v.y;
            As[aCol + 2][row] = v.z; As[aCol + 3][row] = v.w;
        }
        #pragma unroll
        for (int r = 0; r < 2; r++) {
            int row = aRow + r * 64;
            float4 v = *(const float4*)(B + (long)(n0 + row) * K + k0 + aCol);
            Bs[aCol + 0][row] = v.x; Bs[aCol + 1][row] = v.y;
            Bs[aCol + 2][row] = v.z; Bs[aCol + 3][row] = v.w;
        }
        __syncthreads();

        #pragma unroll
        for (int k = 0; k < BK; k++) {
            float4 a0 = *(const float4*)&As[k][ty * 8];
            float4 a1 = *(const float4*)&As[k][ty * 8 + 4];
            float4 b0 = *(const float4*)&Bs[k][tx * 8];
            float4 b1 = *(const float4*)&Bs[k][tx * 8 + 4];
            float a[8] = {a0.x, a0.y, a0.z, a0.w, a1.x, a1.y, a1.z, a1.w};
            float bb[8] = {b0.x, b0.y, b0.z, b0.w, b1.x, b1.y, b1.z, b1.w};
            #pragma unroll
            for (int i = 0; i < 8; i++)
                #pragma unroll
                for (int j = 0; j < 8; j++)
                    acc[i][j] = fmaf(a[i], bb[j], acc[i][j]);
        }
        __syncthreads();
    }

    #pragma unroll
    for (int i = 0; i < 8; i++) {
        const int row = m0 + ty * 8 + i;
        #pragma unroll
        for (int j = 0; j < 8; j += 4) {
            const int col = n0 + tx * 8 + j;
            float4 v = {acc[i][j], acc[i][j+1], acc[i][j+2], acc[i][j+3]};
            *(float4*)(C + (long)row * N + col) = v;
        }
    }
}

// ---------------------------------------------------------------------------
// Flash attention over the "super" head view (fp32 — protects logits).
// ---------------------------------------------------------------------------
__global__ __launch_bounds__(128)
void flash_kernel(const float* __restrict__ Q, const float* __restrict__ Km,
                  const float* __restrict__ Vm, const float* __restrict__ X,
                  const float* __restrict__ scale_param, float* __restrict__ O)
{
    const int b = blockIdx.z, h = blockIdx.y;
    const int t = threadIdx.x;
    const int qrow = blockIdx.x * 128 + t;

    __shared__ __align__(16) float ksh[64][32];
    __shared__ __align__(16) float vsh[64][32];

    const long baseqk = (long)b * L_PER_B + (long)h * (SEQ * HD);
    const float coef = logf(768.0f) * scale_param[h] * 5.656854249492381f;

    float q[32];
    {
        const float4* qp = (const float4*)(Q + baseqk + (long)qrow * HD);
        #pragma unroll
        for (int i = 0; i < 8; i++) {
            float4 v = qp[i];
            q[4 * i]     = v.x * coef;
            q[4 * i + 1] = v.y * coef;
            q[4 * i + 2] = v.z * coef;
            q[4 * i + 3] = v.w * coef;
        }
    }

    float acc[32];
    #pragma unroll
    for (int d = 0; d < 32; d++) acc[d] = 0.0f;
    float Mx = -1e30f, S = 0.0f;

    const int jrow = t >> 1, part = t & 1;

    for (int kt = 0; kt < SEQ / 64; kt++) {
        __syncthreads();
        {
            const float4* src = (const float4*)(Km + baseqk + (long)kt * 64 * HD);
            float4* dst = (float4*)&ksh[0][0];
            #pragma unroll
            for (int i = 0; i < 4; i++) dst[t + i * 128] = src[t + i * 128];
        }
        {
            const float4* vsrc = (const float4*)(Vm + (long)b * L_PER_B +
                                                 (long)(kt * 64 + jrow) * CH + h * HD) + part * 4;
            float4* vdst = (float4*)&vsh[jrow][0] + part * 4;
            #pragma unroll
            for (int i = 0; i < 4; i++) vdst[i] = vsrc[i];
        }
        __syncthreads();

        #pragma unroll
        for (int ch = 0; ch < 2; ch++) {
            float s[32];
            #pragma unroll
            for (int j = 0; j < 32; j++) {
                const float4* kp = (const float4*)&ksh[ch * 32 + j][0];
                float d0 = 0.f, d1 = 0.f, d2 = 0.f, d3 = 0.f;
                #pragma unroll
                for (int i = 0; i < 8; i++) {
                    float4 kv = kp[i];
                    d0 = fmaf(q[4 * i],     kv.x, d0);
                    d1 = fmaf(q[4 * i + 1], kv.y, d1);
                    d2 = fmaf(q[4 * i + 2], kv.z, d2);
                    d3 = fmaf(q[4 * i + 3], kv.w, d3);
                }
                s[j] = (d0 + d1) + (d2 + d3);
            }
            float cm = s[0];
            #pragma unroll
            for (int j = 1; j < 32; j++) cm = fmaxf(cm, s[j]);
            const float Mn = fmaxf(Mx, cm);
            const float corr = __expf(Mx - Mn);
            S *= corr;
            #pragma unroll
            for (int d = 0; d < 32; d++) acc[d] *= corr;
            Mx = Mn;
            #pragma unroll
            for (int j = 0; j < 32; j++) {
                const float p = __expf(s[j] - Mx);
                S += p;
                const float4* vp = (const float4*)&vsh[ch * 32 + j][0];
                #pragma unroll
                for (int i = 0; i < 8; i++) {
                    float4 vv = vp[i];
                    acc[4 * i]     = fmaf(p, vv.x, acc[4 * i]);
                    acc[4 * i + 1] = fmaf(p, vv.y, acc[4 * i + 1]);
                    acc[4 * i + 2] = fmaf(p, vv.z, acc[4 * i + 2]);
                    acc[4 * i + 3] = fmaf(p, vv.w, acc[4 * i + 3]);
                }
            }
        }
    }

    const float inv = 1.0f / S;
    const float4* xp = (const float4*)(X + baseqk + (long)qrow * HD);
    float4* op = (float4*)(O + baseqk + (long)qrow * HD);
    #pragma unroll
    for (int i = 0; i < 8; i++) {
        float4 xv = xp[i];
        float4 ov;
        ov.x = acc[4 * i]     * inv + xv.x;
        ov.y = acc[4 * i + 1] * inv + xv.y;
        ov.z = acc[4 * i + 2] * inv + xv.z;
        ov.w = acc[4 * i + 3] * inv + xv.w;
        op[i] = ov;
    }
}

// ---------------------------------------------------------------------------
// Launch
// ---------------------------------------------------------------------------
extern "C" void kernel_launch(void* const* d_in, const int* in_sizes, int n_in,
                              void* d_out, int out_size)
{
    const float* x     = (const float*)d_in[0];  // (B,N,C)
    const float* scale = (const float*)d_in[1];  // (H)
    const float* Wq    = (const float*)d_in[2];  // (C,C)
    const float* WA    = (const float*)d_in[3];  // (N,N)
    const float* W1    = (const float*)d_in[4];  // (C,C)
    const float* W2    = (const float*)d_in[5];  // (C,C)
    const float* g1    = (const float*)d_in[6];  // (C)
    const float* g2    = (const float*)d_in[7];  // (C)
    float* out = (float*)d_out;

    float *xn, *q, *vp, *vr, *res, *hh, *h1;
    cudaGetSymbolAddress((void**)&xn,  g_xn);
    cudaGetSymbolAddress((void**)&q,   g_q);
    cudaGetSymbolAddress((void**)&vp,  g_vp);
    cudaGetSymbolAddress((void**)&vr,  g_vr);
    cudaGetSymbolAddress((void**)&res, g_res);
    cudaGetSymbolAddress((void**)&hh,  g_h);
    cudaGetSymbolAddress((void**)&h1,  g_h1);

    const int ROWS = BATCH * SEQ;  // 4096

    // 1. xn = rmsnorm(x, g1)
    rmsnorm_kernel<<<ROWS, 256>>>(x, g1, xn);

    // 2. q = xn @ Wq^T   (fp32 — feeds logits)
    gemm128_nt<<<dim3(CH / 128, ROWS / 128, 1), 256>>>(xn, Wq, q, ROWS, CH, CH);

    // 3. gather V' from the (H,N,HD) view
    gather_v_kernel<<<(TOT + 255) / 256, 256>>>(xn, vp);

    // 4. vr[b] = WA @ vp[b]   (tf32 tensor cores; V enters output linearly)
    gemm_tf32<true, 0><<<dim3(CH / 128, SEQ / 128, BATCH), 256>>>(
        WA, vp, vr, nullptr, SEQ, CH, SEQ, 0, (long)SEQ * CH, (long)SEQ * CH);

    // 5. attention (+x residual), fp32
    flash_kernel<<<dim3(SEQ / 128, HEADS, BATCH), 128>>>(q, xn, vr, x, scale, res);

    // 6. hh = rmsnorm(res, g2)
    rmsnorm_kernel<<<ROWS, 256>>>(res, g2, hh);

    // 7. h1 = gelu(hh @ W1^T)   (tf32)
    gemm_tf32<false, 1><<<dim3(CH / 128, ROWS / 128, 1), 256>>>(
        hh, W1, h1, nullptr, ROWS, CH, CH, 0, 0, 0);

    // 8. out = h1 @ W2^T + res  (tf32)
    gemm_tf32<false, 2><<<dim3(CH / 128, ROWS / 128, 1), 256>>>(
        h1, W2, out, res, ROWS, CH, CH, 0, 0, 0);
}

// round 4
// speedup vs baseline: 1.9874x; 1.4307x over previous
#include <cuda_runtime.h>
#include <math.h>

// ---------------------------------------------------------------------------
// Problem constants
// ---------------------------------------------------------------------------
#define BATCH 2
#define SEQ   2048
#define CH    768
#define HEADS 24
#define HD    32
#define L_PER_B (SEQ * CH)
#define TOT (BATCH * SEQ * CH)

__device__ float g_xn[TOT];
__device__ float g_q[TOT];
__device__ float g_vp[TOT];
__device__ float g_vr[TOT];
__device__ float g_res[TOT];
__device__ float g_h[TOT];
__device__ float g_h1[TOT];

// ---------------------------------------------------------------------------
// RMSNorm
// ---------------------------------------------------------------------------
__global__ __launch_bounds__(256)
void rmsnorm_kernel(const float* __restrict__ x, const float* __restrict__ g,
                    float* __restrict__ y)
{
    const int row = blockIdx.x;
    const int t = threadIdx.x;
    const float* xr = x + (long)row * CH;
    float v0 = xr[t], v1 = xr[t + 256], v2 = xr[t + 512];
    float ss = v0 * v0 + v1 * v1 + v2 * v2;

    __shared__ float red[8];
    #pragma unroll
    for (int o = 16; o > 0; o >>= 1) ss += __shfl_xor_sync(0xffffffffu, ss, o);
    if ((t & 31) == 0) red[t >> 5] = ss;
    __syncthreads();
    if (t < 8) {
        float s = red[t];
        #pragma unroll
        for (int o = 4; o > 0; o >>= 1) s += __shfl_xor_sync(0xffu, s, o);
        if (t == 0) red[0] = s;
    }
    __syncthreads();
    const float inv = rsqrtf(red[0] * (1.0f / 768.0f) + 1.1920928955078125e-07f);
    float* yr = y + (long)row * CH;
    yr[t]       = v0 * inv * g[t];
    yr[t + 256] = v1 * inv * g[t + 256];
    yr[t + 512] = v2 * inv * g[t + 512];
}

// ---------------------------------------------------------------------------
// Gather V' from the (H,N,HD) flat view
// ---------------------------------------------------------------------------
__global__ void gather_v_kernel(const float* __restrict__ xn, float* __restrict__ vp)
{
    long i = (long)blockIdx.x * blockDim.x + threadIdx.x;
    if (i >= (long)TOT) return;
    int b = (int)(i / L_PER_B);
    int rem = (int)(i - (long)b * L_PER_B);
    int m = rem / CH;
    int col = rem - m * CH;
    int h = col >> 5;
    int d = col & 31;
    vp[i] = xn[(long)b * L_PER_B + (long)h * (SEQ * HD) + m * HD + d];
}

// ---------------------------------------------------------------------------
// helpers
// ---------------------------------------------------------------------------
__device__ __forceinline__ float gelu_exact(float v)
{
    return 0.5f * v * (1.0f + erff(v * 0.7071067811865476f));
}

__device__ __forceinline__ unsigned cvt_tf32(float x)
{
    unsigned r;
    asm("cvt.rna.tf32.f32 %0, %1;" : "=r"(r) : "f"(x));
    return r;
}

__device__ __forceinline__ float4 cvt4_tf32(float4 v)
{
    float4 s;
    s.x = __uint_as_float(cvt_tf32(v.x));
    s.y = __uint_as_float(cvt_tf32(v.y));
    s.z = __uint_as_float(cvt_tf32(v.z));
    s.w = __uint_as_float(cvt_tf32(v.w));
    return s;
}

// split x = hi + lo (both tf32-representable)
__device__ __forceinline__ void tf32_split(float x, float& hi, float& lo)
{
    hi = __uint_as_float(cvt_tf32(x));
    lo = __uint_as_float(cvt_tf32(x - hi));
}

__device__ __forceinline__ void mma_tf32(float* c, const unsigned* a, const unsigned* b)
{
    asm volatile(
        "mma.sync.aligned.m16n8k8.row.col.f32.tf32.tf32.f32 "
        "{%0,%1,%2,%3}, {%4,%5,%6,%7}, {%8,%9}, {%0,%1,%2,%3};"
        : "+f"(c[0]), "+f"(c[1]), "+f"(c[2]), "+f"(c[3])
        : "r"(a[0]), "r"(a[1]), "r"(a[2]), "r"(a[3]), "r"(b[0]), "r"(b[1]));
}

// ---------------------------------------------------------------------------
// TF32 tensor-core GEMM (single-pass tf32; used where precision allows)
// ---------------------------------------------------------------------------
template<bool NNMODE, int EPI>
__global__ __launch_bounds__(256)
void gemm_tf32(const float* __restrict__ A, const float* __restrict__ B,
               float* __restrict__ C, const float* __restrict__ R,
               int M, int N, int K,
               long sA, long sB, long sC)
{
    __shared__ __align__(16) float As[128 * 36];
    __shared__ __align__(16) float Bs[4608];

    A += (long)blockIdx.z * sA;
    B += (long)blockIdx.z * sB;
    C += (long)blockIdx.z * sC;
    if (EPI == 2) R += (long)blockIdx.z * sC;

    const int t = threadIdx.x;
    const int w = t >> 5, lane = t & 31;
    const int g = lane >> 2, tg = lane & 3;
    const int wm = w >> 2, wn = w & 3;
    const int m0 = blockIdx.y * 128, n0 = blockIdx.x * 128;

    float acc[4][4][4] = {};

    for (int k0 = 0; k0 < K; k0 += 32) {
        #pragma unroll
        for (int i = 0; i < 4; i++) {
            const int row = (t >> 3) + i * 32;
            const int c4 = t & 7;
            float4 v = *(const float4*)(A + (long)(m0 + row) * K + k0 + c4 * 4);
            *(float4*)&As[row * 36 + c4 * 4] = cvt4_tf32(v);
        }
        if (NNMODE) {
            #pragma unroll
            for (int i = 0; i < 4; i++) {
                const int kk = t >> 3;
                const int c4 = (t & 7) + i * 8;
                float4 v = *(const float4*)(B + (long)(k0 + kk) * N + n0 + c4 * 4);
                *(float4*)&Bs[kk * 136 + c4 * 4] = cvt4_tf32(v);
            }
        } else {
            #pragma unroll
            for (int i = 0; i < 4; i++) {
                const int row = (t >> 3) + i * 32;
                const int c4 = t & 7;
                float4 v = *(const float4*)(B + (long)(n0 + row) * K + k0 + c4 * 4);
                *(float4*)&Bs[row * 36 + c4 * 4] = cvt4_tf32(v);
            }
        }
        __syncthreads();

        #pragma unroll
        for (int kc = 0; kc < 4; kc++) {
            const int kb = kc * 8;
            unsigned a[4][4], b[4][2];
            #pragma unroll
            for (int mt = 0; mt < 4; mt++) {
                const int mr = wm * 64 + mt * 16 + g;
                a[mt][0] = __float_as_uint(As[mr * 36 + kb + tg]);
                a[mt][1] = __float_as_uint(As[(mr + 8) * 36 + kb + tg]);
                a[mt][2] = __float_as_uint(As[mr * 36 + kb + tg + 4]);
                a[mt][3] = __float_as_uint(As[(mr + 8) * 36 + kb + tg + 4]);
            }
            #pragma unroll
            for (int nt = 0; nt < 4; nt++) {
                const int nc = wn * 32 + nt * 8 + g;
                if (NNMODE) {
                    b[nt][0] = __float_as_uint(Bs[(kb + tg) * 136 + nc]);
                    b[nt][1] = __float_as_uint(Bs[(kb + tg + 4) * 136 + nc]);
                } else {
                    b[nt][0] = __float_as_uint(Bs[nc * 36 + kb + tg]);
                    b[nt][1] = __float_as_uint(Bs[nc * 36 + kb + tg + 4]);
                }
            }
            #pragma unroll
            for (int mt = 0; mt < 4; mt++)
                #pragma unroll
                for (int nt = 0; nt < 4; nt++)
                    mma_tf32(acc[mt][nt], a[mt], b[nt]);
        }
        __syncthreads();
    }

    #pragma unroll
    for (int mt = 0; mt < 4; mt++) {
        #pragma unroll
        for (int nt = 0; nt < 4; nt++) {
            const int row0 = m0 + wm * 64 + mt * 16 + g;
            const int col  = n0 + wn * 32 + nt * 8 + 2 * tg;
            float v0 = acc[mt][nt][0], v1 = acc[mt][nt][1];
            float v2 = acc[mt][nt][2], v3 = acc[mt][nt][3];
            if (EPI == 1) {
                v0 = gelu_exact(v0); v1 = gelu_exact(v1);
                v2 = gelu_exact(v2); v3 = gelu_exact(v3);
            } else if (EPI == 2) {
                float2 r0 = *(const float2*)(R + (long)row0 * N + col);
                float2 r1 = *(const float2*)(R + (long)(row0 + 8) * N + col);
                v0 += r0.x; v1 += r0.y; v2 += r1.x; v3 += r1.y;
            }
            float2 o0 = {v0, v1}, o1 = {v2, v3};
            *(float2*)(C + (long)row0 * N + col) = o0;
            *(float2*)(C + (long)(row0 + 8) * N + col) = o1;
        }
    }
}

// ---------------------------------------------------------------------------
// FP32 SGEMM (Q projection — feeds logits)
// ---------------------------------------------------------------------------
__global__ __launch_bounds__(256)
void gemm128_nt(const float* __restrict__ A, const float* __restrict__ B,
                float* __restrict__ C, int M, int N, int K)
{
    constexpr int BM = 128, BN = 128, BK = 16;
    __shared__ __align__(16) float As[BK][BM];
    __shared__ __align__(16) float Bs[BK][BN];

    const int tid = threadIdx.x;
    const int m0 = blockIdx.y * BM;
    const int n0 = blockIdx.x * BN;

    const int aRow = tid >> 2;
    const int aCol = (tid & 3) * 4;
    const int tx = tid & 15, ty = tid >> 4;

    float acc[8][8] = {};

    for (int k0 = 0; k0 < K; k0 += BK) {
        #pragma unroll
        for (int r = 0; r < 2; r++) {
            int row = aRow + r * 64;
            float4 v = *(const float4*)(A + (long)(m0 + row) * K + k0 + aCol);
            As[aCol + 0][row] = v.x; As[aCol + 1][row] = v.y;
            As[aCol + 2][row] = v.z; As[aCol + 3][row] = v.w;
        }
        #pragma unroll
        for (int r = 0; r < 2; r++) {
            int row = aRow + r * 64;
            float4 v = *(const float4*)(B + (long)(n0 + row) * K + k0 + aCol);
            Bs[aCol + 0][row] = v.x; Bs[aCol + 1][row] = v.y;
            Bs[aCol + 2][row] = v.z; Bs[aCol + 3][row] = v.w;
        }
        __syncthreads();

        #pragma unroll
        for (int k = 0; k < BK; k++) {
            float4 a0 = *(const float4*)&As[k][ty * 8];
            float4 a1 = *(const float4*)&As[k][ty * 8 + 4];
            float4 b0 = *(const float4*)&Bs[k][tx * 8];
            float4 b1 = *(const float4*)&Bs[k][tx * 8 + 4];
            float a[8] = {a0.x, a0.y, a0.z, a0.w, a1.x, a1.y, a1.z, a1.w};
            float bb[8] = {b0.x, b0.y, b0.z, b0.w, b1.x, b1.y, b1.z, b1.w};
            #pragma unroll
            for (int i = 0; i < 8; i++)
                #pragma unroll
                for (int j = 0; j < 8; j++)
                    acc[i][j] = fmaf(a[i], bb[j], acc[i][j]);
        }
        __syncthreads();
    }

    #pragma unroll
    for (int i = 0; i < 8; i++) {
        const int row = m0 + ty * 8 + i;
        #pragma unroll
        for (int j = 0; j < 8; j += 4) {
            const int col = n0 + tx * 8 + j;
            float4 v = {acc[i][j], acc[i][j+1], acc[i][j+2], acc[i][j+3]};
            *(float4*)(C + (long)row * N + col) = v;
        }
    }
}

// ---------------------------------------------------------------------------
// Tensor-core flash attention, 3xTF32 error-compensated (fp32-accurate).
// Block: 256 threads (8 warps), Br=128 query rows (warp m16), Bc=64 keys/iter.
// ---------------------------------------------------------------------------
#define KSH_HI 0
#define KSH_LO (KSH_HI + 64 * 36)
#define VSH_HI (KSH_LO + 64 * 36)
#define VSH_LO (VSH_HI + 64 * 40)
#define PSH_HI (VSH_LO + 64 * 40)
#define PSH_LO (PSH_HI + 128 * 68)
#define FLASH_SMEM_FLOATS (PSH_LO + 128 * 68)

__global__ __launch_bounds__(256)
void flash_tc(const float* __restrict__ Q, const float* __restrict__ Km,
              const float* __restrict__ Vm, const float* __restrict__ X,
              const float* __restrict__ scale_param, float* __restrict__ O)
{
    extern __shared__ float sm[];
    float* ksh_hi = sm + KSH_HI;
    float* ksh_lo = sm + KSH_LO;
    float* vsh_hi = sm + VSH_HI;
    float* vsh_lo = sm + VSH_LO;
    float* psh_hi = sm + PSH_HI;
    float* psh_lo = sm + PSH_LO;

    const int b = blockIdx.z, h = blockIdx.y;
    const int t = threadIdx.x, w = t >> 5, lane = t & 31;
    const int g = lane >> 2, tg = lane & 3;
    const long baseqk = (long)b * L_PER_B + (long)h * (SEQ * HD);
    const int qblk = blockIdx.x * 128;
    const float coef = logf(768.0f) * scale_param[h] * 5.656854249492381f;

    const int row0 = qblk + w * 16 + g;   // global q row (this thread, part 0)
    const int prow0 = w * 16 + g;         // row within block

    // ---- Q fragments (loop-invariant), coef folded, hi/lo split ----
    unsigned qhi[4][4], qlo[4][4];
    #pragma unroll
    for (int kc = 0; kc < 4; kc++) {
        #pragma unroll
        for (int rr = 0; rr < 2; rr++) {
            const long base = baseqk + (long)(row0 + rr * 8) * HD + kc * 8 + tg;
            float x0 = Q[base] * coef;
            float x1 = Q[base + 4] * coef;
            float h0, l0, h1, l1;
            tf32_split(x0, h0, l0);
            tf32_split(x1, h1, l1);
            qhi[kc][rr]     = __float_as_uint(h0);
            qhi[kc][rr + 2] = __float_as_uint(h1);
            qlo[kc][rr]     = __float_as_uint(l0);
            qlo[kc][rr + 2] = __float_as_uint(l1);
        }
    }

    float acco[4][4] = {};
    float Mx[2] = {-1e30f, -1e30f};
    float Srun[2] = {0.0f, 0.0f};

    for (int kt = 0; kt < SEQ / 64; kt++) {
        __syncthreads();
        // ---- stage K tile (64 x 32) hi/lo ----
        #pragma unroll
        for (int i = 0; i < 2; i++) {
            const int f = t + i * 256;         // float4 index, 512 total
            const int row = f >> 3, d4 = (f & 7) * 4;
            float4 v = *(const float4*)(Km + baseqk + (long)(kt * 64 + row) * HD + d4);
            float4 hi, lo;
            tf32_split(v.x, hi.x, lo.x); tf32_split(v.y, hi.y, lo.y);
            tf32_split(v.z, hi.z, lo.z); tf32_split(v.w, hi.w, lo.w);
            *(float4*)&ksh_hi[row * 36 + d4] = hi;
            *(float4*)&ksh_lo[row * 36 + d4] = lo;
        }
        // ---- stage V tile (64 x 32) hi/lo ----
        #pragma unroll
        for (int i = 0; i < 2; i++) {
            const int f = t + i * 256;
            const int row = f >> 3, d4 = (f & 7) * 4;
            float4 v = *(const float4*)(Vm + (long)b * L_PER_B +
                                        (long)(kt * 64 + row) * CH + h * HD + d4);
            float4 hi, lo;
            tf32_split(v.x, hi.x, lo.x); tf32_split(v.y, hi.y, lo.y);
            tf32_split(v.z, hi.z, lo.z); tf32_split(v.w, hi.w, lo.w);
            *(float4*)&vsh_hi[row * 40 + d4] = hi;
            *(float4*)&vsh_lo[row * 40 + d4] = lo;
        }
        __syncthreads();

        // ---- S = Q K^T (3xTF32) ----
        float accs[8][4] = {};
        #pragma unroll
        for (int kc = 0; kc < 4; kc++) {
            const int kb = kc * 8;
            #pragma unroll
            for (int nt = 0; nt < 8; nt++) {
                const int key = nt * 8 + g;
                unsigned bhi[2], blo[2];
                bhi[0] = __float_as_uint(ksh_hi[key * 36 + kb + tg]);
                bhi[1] = __float_as_uint(ksh_hi[key * 36 + kb + tg + 4]);
                blo[0] = __float_as_uint(ksh_lo[key * 36 + kb + tg]);
                blo[1] = __float_as_uint(ksh_lo[key * 36 + kb + tg + 4]);
                mma_tf32(accs[nt], qhi[kc], bhi);
                mma_tf32(accs[nt], qhi[kc], blo);
                mma_tf32(accs[nt], qlo[kc], bhi);
            }
        }

        // ---- online softmax (per-row over the 4 quad lanes) ----
        #pragma unroll
        for (int rr = 0; rr < 2; rr++) {
            const int i0 = rr * 2, i1 = rr * 2 + 1;
            float m = accs[0][i0];
            #pragma unroll
            for (int nt = 0; nt < 8; nt++) {
                m = fmaxf(m, accs[nt][i0]);
                m = fmaxf(m, accs[nt][i1]);
            }
            m = fmaxf(m, __shfl_xor_sync(0xffffffffu, m, 1));
            m = fmaxf(m, __shfl_xor_sync(0xffffffffu, m, 2));
            const float Mn = fmaxf(Mx[rr], m);
            const float corr = __expf(Mx[rr] - Mn);
            Srun[rr] *= corr;
            #pragma unroll
            for (int nt = 0; nt < 4; nt++) {
                acco[nt][i0] *= corr;
                acco[nt][i1] *= corr;
            }
            Mx[rr] = Mn;
            float lsum = 0.0f;
            const int pr = (prow0 + rr * 8) * 68;
            #pragma unroll
            for (int nt = 0; nt < 8; nt++) {
                const float p0 = __expf(accs[nt][i0] - Mn);
                const float p1 = __expf(accs[nt][i1] - Mn);
                lsum += p0 + p1;
                float h0, l0, h1, l1;
                tf32_split(p0, h0, l0);
                tf32_split(p1, h1, l1);
                const int col = nt * 8 + 2 * tg;
                float2 ph = {h0, h1}, pl = {l0, l1};
                *(float2*)&psh_hi[pr + col] = ph;
                *(float2*)&psh_lo[pr + col] = pl;
            }
            lsum += __shfl_xor_sync(0xffffffffu, lsum, 1);
            lsum += __shfl_xor_sync(0xffffffffu, lsum, 2);
            Srun[rr] += lsum;
        }
        __syncwarp();

        // ---- O += P V (3xTF32) ----
        #pragma unroll
        for (int kc = 0; kc < 8; kc++) {
            const int kb = kc * 8;
            unsigned phi[4], plo[4];
            phi[0] = __float_as_uint(psh_hi[prow0 * 68 + kb + tg]);
            phi[1] = __float_as_uint(psh_hi[(prow0 + 8) * 68 + kb + tg]);
            phi[2] = __float_as_uint(psh_hi[prow0 * 68 + kb + tg + 4]);
            phi[3] = __float_as_uint(psh_hi[(prow0 + 8) * 68 + kb + tg + 4]);
            plo[0] = __float_as_uint(psh_lo[prow0 * 68 + kb + tg]);
            plo[1] = __float_as_uint(psh_lo[(prow0 + 8) * 68 + kb + tg]);
            plo[2] = __float_as_uint(psh_lo[prow0 * 68 + kb + tg + 4]);
            plo[3] = __float_as_uint(psh_lo[(prow0 + 8) * 68 + kb + tg + 4]);
            #pragma unroll
            for (int nt = 0; nt < 4; nt++) {
                unsigned bhi[2], blo[2];
                bhi[0] = __float_as_uint(vsh_hi[(kb + tg) * 40 + nt * 8 + g]);
                bhi[1] = __float_as_uint(vsh_hi[(kb + tg + 4) * 40 + nt * 8 + g]);
                blo[0] = __float_as_uint(vsh_lo[(kb + tg) * 40 + nt * 8 + g]);
                blo[1] = __float_as_uint(vsh_lo[(kb + tg + 4) * 40 + nt * 8 + g]);
                mma_tf32(acco[nt], phi, bhi);
                mma_tf32(acco[nt], phi, blo);
                mma_tf32(acco[nt], plo, bhi);
            }
        }
    }

    // ---- epilogue: /S, +x, store ----
    const float inv0 = 1.0f / Srun[0];
    const float inv1 = 1.0f / Srun[1];
    #pragma unroll
    for (int nt = 0; nt < 4; nt++) {
        const int col = nt * 8 + 2 * tg;
        const long a0 = baseqk + (long)row0 * HD + col;
        const long a1 = baseqk + (long)(row0 + 8) * HD + col;
        float2 x0 = *(const float2*)(X + a0);
        float2 x1 = *(const float2*)(X + a1);
        float2 o0 = {acco[nt][0] * inv0 + x0.x, acco[nt][1] * inv0 + x0.y};
        float2 o1 = {acco[nt][2] * inv1 + x1.x, acco[nt][3] * inv1 + x1.y};
        *(float2*)(O + a0) = o0;
        *(float2*)(O + a1) = o1;
    }
}

// ---------------------------------------------------------------------------
// Launch
// ---------------------------------------------------------------------------
extern "C" void kernel_launch(void* const* d_in, const int* in_sizes, int n_in,
                              void* d_out, int out_size)
{
    const float* x     = (const float*)d_in[0];
    const float* scale = (const float*)d_in[1];
    const float* Wq    = (const float*)d_in[2];
    const float* WA    = (const float*)d_in[3];
    const float* W1    = (const float*)d_in[4];
    const float* W2    = (const float*)d_in[5];
    const float* g1    = (const float*)d_in[6];
    const float* g2    = (const float*)d_in[7];
    float* out = (float*)d_out;

    float *xn, *q, *vp, *vr, *res, *hh, *h1;
    cudaGetSymbolAddress((void**)&xn,  g_xn);
    cudaGetSymbolAddress((void**)&q,   g_q);
    cudaGetSymbolAddress((void**)&vp,  g_vp);
    cudaGetSymbolAddress((void**)&vr,  g_vr);
    cudaGetSymbolAddress((void**)&res, g_res);
    cudaGetSymbolAddress((void**)&hh,  g_h);
    cudaGetSymbolAddress((void**)&h1,  g_h1);

    const int ROWS = BATCH * SEQ;  // 4096
    const int flashSmem = FLASH_SMEM_FLOATS * 4;
    cudaFuncSetAttribute(flash_tc, cudaFuncAttributeMaxDynamicSharedMemorySize,
                         flashSmem);

    // 1. xn = rmsnorm(x, g1)
    rmsnorm_kernel<<<ROWS, 256>>>(x, g1, xn);

    // 2. q = xn @ Wq^T   (fp32 — feeds logits)
    gemm128_nt<<<dim3(CH / 128, ROWS / 128, 1), 256>>>(xn, Wq, q, ROWS, CH, CH);

    // 3. gather V'
    gather_v_kernel<<<(TOT + 255) / 256, 256>>>(xn, vp);

    // 4. vr[b] = WA @ vp[b]   (tf32)
    gemm_tf32<true, 0><<<dim3(CH / 128, SEQ / 128, BATCH), 256>>>(
        WA, vp, vr, nullptr, SEQ, CH, SEQ, 0, (long)SEQ * CH, (long)SEQ * CH);

    // 5. attention (+x residual), tensor-core 3xTF32
    flash_tc<<<dim3(SEQ / 128, HEADS, BATCH), 256, flashSmem>>>(
        q, xn, vr, x, scale, res);

    // 6. hh = rmsnorm(res, g2)
    rmsnorm_kernel<<<ROWS, 256>>>(res, g2, hh);

    // 7. h1 = gelu(hh @ W1^T)   (tf32)
    gemm_tf32<false, 1><<<dim3(CH / 128, ROWS / 128, 1), 256>>>(
        hh, W1, h1, nullptr, ROWS, CH, CH, 0, 0, 0);

    // 8. out = h1 @ W2^T + res  (tf32)
    gemm_tf32<false, 2><<<dim3(CH / 128, ROWS / 128, 1), 256>>>(
        h1, W2, out, res, ROWS, CH, CH, 0, 0, 0);
}